// round 1
// baseline (speedup 1.0000x reference)
#include <cuda_runtime.h>
#include <math.h>

#define S_ 256
#define B_ 512
#define H_ 256
#define H3 768
#define VOCAB_ 32000
#define NSTACK 2
#define SSIZE 64
#define ELEM 64

// ---------------- device scratch (static, no allocation) ----------------
__device__ float g_EMB_GI[VOCAB_ * H3];     // emb @ W_ih^T + b_ih, per vocab row (98MB)
__device__ float g_WihT[H_ * H3];
__device__ float g_WhhT[H_ * H3];
__device__ float g_WstkT[H_ * (NSTACK * ELEM)];
__device__ float g_Wa1T[H_ * H_];
__device__ float g_h[4][B_ * H_];           // hidden ring buffer
__device__ float g_PV[2][B_ * NSTACK * ELEM]; // push_vals ping-pong
__device__ float g_T[(size_t)S_ * B_ * H_]; // tanh(outputs@Wa1^T+ba1) scratch (134MB)
__device__ float g_scores[S_ * B_];

__device__ __forceinline__ float sigmoidf_(float x) { return 1.f / (1.f + expf(-x)); }

// ---------------- transpose: dst[c*R + r] = src[r*C + c] ----------------
__global__ void transpose_k(const float* __restrict__ src, int which, int R, int C) {
    int idx = blockIdx.x * blockDim.x + threadIdx.x;
    if (idx >= R * C) return;
    float* dst = (which == 0) ? g_WihT : (which == 1) ? g_WhhT : (which == 2) ? g_WstkT : g_Wa1T;
    int r = idx % R, c = idx / R;
    dst[idx] = src[r * C + c];
}

// ---------------- init: h0 = 0, stacks = broadcast(empty_elem) ----------------
__global__ void init_k(float* __restrict__ stacks, const float* __restrict__ empty_elem) {
    int idx = blockIdx.x * blockDim.x + threadIdx.x;
    if (idx < B_ * H_) g_h[0][idx] = 0.f;
    if (idx < B_ * NSTACK * SSIZE * ELEM) stacks[idx] = empty_elem[idx & (ELEM - 1)];
}

// ---------------- tiled SGEMM: C = act(A[MxK] @ B[KxN] + bias[N]) ----------------
// BM=64, BN=64, BK=16, 256 threads, 4x4 per thread. M%64==0, N%64==0, K%16==0.
template <bool TANH>
__global__ void __launch_bounds__(256) sgemm64_k(
    const float* __restrict__ A, const float* __restrict__ Bm,
    const float* __restrict__ bias, float* __restrict__ C,
    int M, int N, int K)
{
    __shared__ float As[16 * 64];  // [k][m]
    __shared__ float Bs[16 * 64];  // [k][n]
    int tid = threadIdx.x;
    int m0 = blockIdx.y * 64, n0 = blockIdx.x * 64;
    int tx = tid & 15, ty = tid >> 4;
    float acc[4][4] = {};
    for (int k0 = 0; k0 < K; k0 += 16) {
        {
            int m = tid & 63, kb = tid >> 6;
#pragma unroll
            for (int r = 0; r < 4; r++) {
                int k = kb + r * 4;
                As[k * 64 + m] = A[(size_t)(m0 + m) * K + k0 + k];
            }
        }
        {
            int k = tid >> 4, nq = (tid & 15) * 4;
            *(float4*)&Bs[k * 64 + nq] = *(const float4*)&Bm[(size_t)(k0 + k) * N + n0 + nq];
        }
        __syncthreads();
#pragma unroll
        for (int kk = 0; kk < 16; kk++) {
            float a[4], bb[4];
#pragma unroll
            for (int i = 0; i < 4; i++) a[i] = As[kk * 64 + ty * 4 + i];
#pragma unroll
            for (int j = 0; j < 4; j++) bb[j] = Bs[kk * 64 + tx * 4 + j];
#pragma unroll
            for (int i = 0; i < 4; i++)
#pragma unroll
                for (int j = 0; j < 4; j++) acc[i][j] += a[i] * bb[j];
        }
        __syncthreads();
    }
#pragma unroll
    for (int i = 0; i < 4; i++) {
        int m = m0 + ty * 4 + i;
        int n = n0 + tx * 4;
        float4 o;
        o.x = acc[i][0] + bias[n + 0];
        o.y = acc[i][1] + bias[n + 1];
        o.z = acc[i][2] + bias[n + 2];
        o.w = acc[i][3] + bias[n + 3];
        if (TANH) { o.x = tanhf(o.x); o.y = tanhf(o.y); o.z = tanhf(o.z); o.w = tanhf(o.w); }
        *(float4*)&C[(size_t)m * N + n] = o;
    }
}

// ---------------- fused per-step kernel ----------------
// blocks [0,128):    GRU  gh = h_s @ W_hh^T (3 gates), epilogue -> h_{s+1}, outputs[s]
// blocks [128,160):  AUX  PV_s = tanh(h_s @ W_stk^T + b_stk)
// blocks [160,1184): STACK update for step s-1 (uses h_{s-1}, PV_{s-1})
#define GRU_BLOCKS 128
#define AUX_BLOCKS 32
#define STEP_BLOCKS (GRU_BLOCKS + AUX_BLOCKS + B_ * NSTACK)

__global__ void __launch_bounds__(256) step_kernel(
    int s,
    const int* __restrict__ tokens,
    const float* __restrict__ b_ih,
    const float* __restrict__ b_hh,
    const float* __restrict__ W_act,
    const float* __restrict__ b_act,
    const float* __restrict__ b_stk,
    const float* __restrict__ empty_elem,
    float* __restrict__ outputs,
    float* __restrict__ stacks)
{
    __shared__ float sm[4480];
    int tid = threadIdx.x;
    int blk = blockIdx.x;

    if (blk < GRU_BLOCKS) {
        if (s >= S_) return;
        const float* hin = g_h[s & 3];
        float* hout = g_h[(s + 1) & 3];
        float* As = sm;            // [32][32] : As[k*32+m]
        float* Bs = sm + 1024;     // [3][32][32]
        int b0 = (blk >> 3) * 32;
        int j0 = (blk & 7) * 32;
        int tx = tid & 15, ty = tid >> 4;
        float acc[3][2][2] = {};
        for (int k0 = 0; k0 < H_; k0 += 32) {
            {
                int m = tid & 31, kb = tid >> 5;
#pragma unroll
                for (int r = 0; r < 4; r++) {
                    int k = kb + r * 8;
                    As[k * 32 + m] = hin[(b0 + m) * H_ + k0 + k];
                }
            }
            {
                int kk = tid >> 3, jq = (tid & 7) * 4;
#pragma unroll
                for (int g = 0; g < 3; g++) {
                    float4 v = *(const float4*)&g_WhhT[(k0 + kk) * H3 + g * H_ + j0 + jq];
                    *(float4*)&Bs[(g * 32 + kk) * 32 + jq] = v;
                }
            }
            __syncthreads();
#pragma unroll
            for (int kk = 0; kk < 32; kk++) {
                float a0 = As[kk * 32 + ty * 2];
                float a1 = As[kk * 32 + ty * 2 + 1];
#pragma unroll
                for (int g = 0; g < 3; g++) {
                    float bb0 = Bs[(g * 32 + kk) * 32 + tx * 2];
                    float bb1 = Bs[(g * 32 + kk) * 32 + tx * 2 + 1];
                    acc[g][0][0] += a0 * bb0; acc[g][0][1] += a0 * bb1;
                    acc[g][1][0] += a1 * bb0; acc[g][1][1] += a1 * bb1;
                }
            }
            __syncthreads();
        }
#pragma unroll
        for (int i = 0; i < 2; i++) {
            int b = b0 + ty * 2 + i;
            int tok = tokens[s * B_ + b];
            const float* gi = (tok == 0) ? b_ih : (g_EMB_GI + (size_t)tok * H3);
#pragma unroll
            for (int j2 = 0; j2 < 2; j2++) {
                int j = j0 + tx * 2 + j2;
                float ghr = acc[0][i][j2] + b_hh[j];
                float ghz = acc[1][i][j2] + b_hh[H_ + j];
                float ghn = acc[2][i][j2] + b_hh[2 * H_ + j];
                float r = sigmoidf_(gi[j] + ghr);
                float z = sigmoidf_(gi[H_ + j] + ghz);
                float n = tanhf(gi[2 * H_ + j] + r * ghn);
                float hp = hin[b * H_ + j];
                float hn = (1.f - z) * n + z * hp;
                hout[b * H_ + j] = hn;
                outputs[((size_t)s * B_ + b) * H_ + j] = hn;
            }
        }
        return;
    }

    if (blk < GRU_BLOCKS + AUX_BLOCKS) {
        if (s >= S_) return;
        int ab = blk - GRU_BLOCKS;
        const float* hin = g_h[s & 3];
        float* pvout = g_PV[s & 1];
        int b0 = (ab >> 1) * 32;
        int c0 = (ab & 1) * 64;
        float* As = sm;          // [16][32]
        float* Bs = sm + 512;    // [16][64]
        int tx = tid & 15, ty = tid >> 4;
        float acc[2][4] = {};
        for (int k0 = 0; k0 < H_; k0 += 16) {
            {
                int m = tid & 31, kb = tid >> 5;
#pragma unroll
                for (int r = 0; r < 2; r++) {
                    int k = kb + r * 8;
                    As[k * 32 + m] = hin[(b0 + m) * H_ + k0 + k];
                }
            }
            {
                int k = tid >> 4, nq = (tid & 15) * 4;
                *(float4*)&Bs[k * 64 + nq] =
                    *(const float4*)&g_WstkT[(k0 + k) * (NSTACK * ELEM) + c0 + nq];
            }
            __syncthreads();
#pragma unroll
            for (int kk = 0; kk < 16; kk++) {
                float a0 = As[kk * 32 + ty * 2], a1 = As[kk * 32 + ty * 2 + 1];
                float4 bv = *(float4*)&Bs[kk * 64 + tx * 4];
                acc[0][0] += a0 * bv.x; acc[0][1] += a0 * bv.y;
                acc[0][2] += a0 * bv.z; acc[0][3] += a0 * bv.w;
                acc[1][0] += a1 * bv.x; acc[1][1] += a1 * bv.y;
                acc[1][2] += a1 * bv.z; acc[1][3] += a1 * bv.w;
            }
            __syncthreads();
        }
#pragma unroll
        for (int i = 0; i < 2; i++) {
            int b = b0 + ty * 2 + i;
#pragma unroll
            for (int j = 0; j < 4; j++) {
                int c = c0 + tx * 4 + j;
                pvout[b * (NSTACK * ELEM) + c] = tanhf(acc[i][j] + b_stk[c]);
            }
        }
        return;
    }

    // ---- stack update for step s-1 ----
    {
        if (s == 0) return;
        int sb = blk - GRU_BLOCKS - AUX_BLOCKS;
        int b = sb >> 1, n = sb & 1;
        const float* hprev = g_h[(s - 1) & 3];
        const float* pv = g_PV[(s - 1) & 1] + b * (NSTACK * ELEM) + n * ELEM;
        float* gst = stacks + ((size_t)(b * NSTACK + n) << 12);  // 64*64
        float* Ss = sm;                  // [64][65]
        float* hsm = sm + 64 * 65;       // 256
        float* red = hsm + 256;          // 8

        hsm[tid] = hprev[b * H_ + tid];
#pragma unroll
        for (int r = 0; r < 16; r++) {
            int idx = tid + r * 256;
            Ss[(idx >> 6) * 65 + (idx & 63)] = gst[idx];
        }
        __syncthreads();

        if (tid < 96) {
            int w = tid >> 5, lane = tid & 31;
            const float* wr = W_act + (n * 3 + w) * H_;
            float sum = 0.f;
#pragma unroll
            for (int k = lane; k < H_; k += 32) sum += hsm[k] * wr[k];
#pragma unroll
            for (int off = 16; off > 0; off >>= 1) sum += __shfl_xor_sync(0xffffffffu, sum, off);
            if (lane == 0) red[w] = sum + b_act[n * 3 + w];
        }
        __syncthreads();
        if (tid == 0) {
            float l0 = red[0], l1 = red[1], l2 = red[2];
            float mx = fmaxf(l0, fmaxf(l1, l2));
            float e0 = expf(l0 - mx), e1 = expf(l1 - mx), e2 = expf(l2 - mx);
            float inv = 1.f / (e0 + e1 + e2);
            red[4] = e0 * inv; red[5] = e1 * inv; red[6] = e2 * inv;
        }
        __syncthreads();
        float ppush = red[4], ppop = red[5], pnoop = red[6];
        int e = tid & 63;
        int rb = (tid >> 6) * 16;
        float pve = ppush * pv[e];
        float emp = empty_elem[e];
#pragma unroll
        for (int r = 0; r < 16; r++) {
            int i = rb + r;
            float v;
            if (i == 0)            v = pve;
            else if (i == SSIZE-1) v = emp;
            else v = ppush * Ss[(i - 1) * 65 + e] + ppop * Ss[(i + 1) * 65 + e]
                   + pnoop * Ss[i * 65 + e];
            gst[i * ELEM + e] = v;
        }
    }
}

// ---------------- attention scores: g_scores[row] = g_T[row] . Wa2 + ba2 (masked) ----------------
__global__ void score_k(const float* __restrict__ Wa2, const float* __restrict__ ba2,
                        const int* __restrict__ tokens) {
    int row = blockIdx.x * 8 + (threadIdx.x >> 5);
    int lane = threadIdx.x & 31;
    const float* t = g_T + (size_t)row * H_;
    float sum = 0.f;
#pragma unroll
    for (int k = lane; k < H_; k += 32) sum += t[k] * Wa2[k];
#pragma unroll
    for (int off = 16; off > 0; off >>= 1) sum += __shfl_xor_sync(0xffffffffu, sum, off);
    if (lane == 0) {
        float v = sum + ba2[0];
        if (tokens[row] == 0) v = -1e30f;
        g_scores[row] = v;
    }
}

// ---------------- softmax over S + weighted sum -> final_hidden ----------------
__global__ void __launch_bounds__(256) attn_final_k(const float* __restrict__ outputs,
                                                    float* __restrict__ fh) {
    int b = blockIdx.x;
    int tid = threadIdx.x;           // = s index
    int lane = tid & 31, wid = tid >> 5;
    __shared__ float a_sm[S_];
    __shared__ float rmax[8];
    __shared__ float rsum[8];

    float v = g_scores[tid * B_ + b];
    float m = v;
#pragma unroll
    for (int off = 16; off > 0; off >>= 1) m = fmaxf(m, __shfl_xor_sync(0xffffffffu, m, off));
    if (lane == 0) rmax[wid] = m;
    __syncthreads();
    float mx = rmax[0];
#pragma unroll
    for (int i = 1; i < 8; i++) mx = fmaxf(mx, rmax[i]);
    float e = expf(v - mx);
    float sum = e;
#pragma unroll
    for (int off = 16; off > 0; off >>= 1) sum += __shfl_xor_sync(0xffffffffu, sum, off);
    if (lane == 0) rsum[wid] = sum;
    __syncthreads();
    float tot = rsum[0];
#pragma unroll
    for (int i = 1; i < 8; i++) tot += rsum[i];
    a_sm[tid] = e / tot;
    __syncthreads();

    float acc = 0.f;
    for (int s2 = 0; s2 < S_; s2++)
        acc += a_sm[s2] * outputs[((size_t)s2 * B_ + b) * H_ + tid];
    fh[b * H_ + tid] = acc;
}

// ---------------- launch ----------------
extern "C" void kernel_launch(void* const* d_in, const int* in_sizes, int n_in,
                              void* d_out, int out_size) {
    const int*   tokens     = (const int*)d_in[0];
    const float* emb        = (const float*)d_in[1];
    const float* W_ih       = (const float*)d_in[2];
    const float* W_hh       = (const float*)d_in[3];
    const float* b_ih       = (const float*)d_in[4];
    const float* b_hh       = (const float*)d_in[5];
    const float* W_act      = (const float*)d_in[6];
    const float* b_act      = (const float*)d_in[7];
    const float* W_stk      = (const float*)d_in[8];
    const float* b_stk      = (const float*)d_in[9];
    const float* empty_elem = (const float*)d_in[10];
    // d_in[11] = W_up, d_in[12] = W_down : shift matrices, hardcoded
    const float* Wa1        = (const float*)d_in[13];
    const float* ba1        = (const float*)d_in[14];
    const float* Wa2        = (const float*)d_in[15];
    const float* ba2        = (const float*)d_in[16];

    float* out     = (float*)d_out;
    float* outputs = out;
    float* fh      = out + (size_t)S_ * B_ * H_;
    float* stacks  = fh + (size_t)B_ * H_;

    float *pWihT, *pWa1T, *pEMB, *pT;
    cudaGetSymbolAddress((void**)&pWihT, g_WihT);
    cudaGetSymbolAddress((void**)&pWa1T, g_Wa1T);
    cudaGetSymbolAddress((void**)&pEMB,  g_EMB_GI);
    cudaGetSymbolAddress((void**)&pT,    g_T);

    // weight transposes
    transpose_k<<<(H3 * H_ + 255) / 256, 256>>>(W_ih, 0, H3, H_);
    transpose_k<<<(H3 * H_ + 255) / 256, 256>>>(W_hh, 1, H3, H_);
    transpose_k<<<(NSTACK * ELEM * H_ + 255) / 256, 256>>>(W_stk, 2, NSTACK * ELEM, H_);
    transpose_k<<<(H_ * H_ + 255) / 256, 256>>>(Wa1, 3, H_, H_);

    // init h0 and stacks
    init_k<<<(B_ * NSTACK * SSIZE * ELEM + 255) / 256, 256>>>(stacks, empty_elem);

    // EMB_GI = emb @ W_ih^T + b_ih  (32000 x 768)
    {
        dim3 grid(H3 / 64, VOCAB_ / 64);
        sgemm64_k<false><<<grid, 256>>>(emb, pWihT, b_ih, pEMB, VOCAB_, H3, H_);
    }

    // recurrence: 256 steps + 1 tail launch for the final stack update
    for (int s = 0; s <= S_; s++) {
        step_kernel<<<STEP_BLOCKS, 256>>>(s, tokens, b_ih, b_hh, W_act, b_act,
                                          b_stk, empty_elem, outputs, stacks);
    }

    // attention
    {
        dim3 grid(H_ / 64, (S_ * B_) / 64);
        sgemm64_k<true><<<grid, 256>>>(outputs, pWa1T, ba1, pT, S_ * B_, H_, H_);
    }
    score_k<<<(S_ * B_) / 8, 256>>>(Wa2, ba2, tokens);
    attn_final_k<<<B_, 256>>>(outputs, fh);
}

// round 2
// speedup vs baseline: 1.3860x; 1.3860x over previous
#include <cuda_runtime.h>
#include <math.h>

#define S_ 256
#define B_ 512
#define H_ 256
#define H3 768
#define VOCAB_ 32000
#define NSTACK 2
#define SSIZE 64
#define ELEM 64

// ---------------- device scratch (static, no allocation) ----------------
__device__ float g_EMB_GI[VOCAB_ * H3];       // emb @ W_ih^T + b_ih  (98 MB)
__device__ float g_WihT[H_ * H3];
__device__ float g_WhhT[H_ * H3];
__device__ float g_WstkT[H_ * (NSTACK * ELEM)];
__device__ float g_Wa1T[H_ * H_];
__device__ float g_h[4][B_ * H_];             // hidden ring buffer
__device__ float g_PV[2][B_ * NSTACK * ELEM]; // push_vals ping-pong
__device__ float g_P[2][B_ * NSTACK * 3];     // act probs ping-pong
__device__ float g_T[(size_t)S_ * B_ * H_];   // tanh(outputs@Wa1^T+ba1) scratch
__device__ float g_scores[S_ * B_];

__device__ __forceinline__ float sigmoidf_(float x) { return 1.f / (1.f + expf(-x)); }

// ---------------- transpose: dst[c*R + r] = src[r*C + c] ----------------
__global__ void transpose_k(const float* __restrict__ src, int which, int R, int C) {
    int idx = blockIdx.x * blockDim.x + threadIdx.x;
    if (idx >= R * C) return;
    float* dst = (which == 0) ? g_WihT : (which == 1) ? g_WhhT : (which == 2) ? g_WstkT : g_Wa1T;
    int r = idx % R, c = idx / R;
    dst[idx] = src[r * C + c];
}

// ---------------- init: h0 = 0, stacks = broadcast(empty_elem) ----------------
__global__ void init_k(float* __restrict__ stacks, const float* __restrict__ empty_elem) {
    int idx = blockIdx.x * blockDim.x + threadIdx.x;
    if (idx < B_ * H_) g_h[0][idx] = 0.f;
    if (idx < B_ * NSTACK * SSIZE * ELEM) stacks[idx] = empty_elem[idx & (ELEM - 1)];
}

// ---------------- 128x128x16 SGEMM: C = act(A[MxK] @ B[KxN] + bias[N]) ----------------
// 256 threads, 8x8 per thread (split 4+4 with offset 64). M%128==0, N%128==0, K%16==0.
template <bool TANH>
__global__ void __launch_bounds__(256) sgemm128_k(
    const float* __restrict__ A, const float* __restrict__ Bm,
    const float* __restrict__ bias, float* __restrict__ C,
    int M, int N, int K)
{
    __shared__ float As[16][128];   // [k][m]
    __shared__ float Bs[16][128];   // [k][n]
    int tid = threadIdx.x;
    int m0 = blockIdx.y * 128, n0 = blockIdx.x * 128;
    int tx = tid & 15, ty = tid >> 4;

    float acc[2][2][4][4] = {};     // [ichunk][jchunk][i][j]

    for (int k0 = 0; k0 < K; k0 += 16) {
#pragma unroll
        for (int i = 0; i < 2; i++) {
            int f = tid * 2 + i;
            int arow = f >> 2, aq = (f & 3) * 4;
            float4 v = *(const float4*)&A[(size_t)(m0 + arow) * K + k0 + aq];
            As[aq + 0][arow] = v.x; As[aq + 1][arow] = v.y;
            As[aq + 2][arow] = v.z; As[aq + 3][arow] = v.w;
            int brow = f >> 5, bc = (f & 31) * 4;
            *(float4*)&Bs[brow][bc] = *(const float4*)&Bm[(size_t)(k0 + brow) * N + n0 + bc];
        }
        __syncthreads();
#pragma unroll
        for (int kk = 0; kk < 16; kk++) {
            float a[2][4], b[2][4];
            *(float4*)a[0] = *(float4*)&As[kk][ty * 4];
            *(float4*)a[1] = *(float4*)&As[kk][ty * 4 + 64];
            *(float4*)b[0] = *(float4*)&Bs[kk][tx * 4];
            *(float4*)b[1] = *(float4*)&Bs[kk][tx * 4 + 64];
#pragma unroll
            for (int ic = 0; ic < 2; ic++)
#pragma unroll
                for (int jc = 0; jc < 2; jc++)
#pragma unroll
                    for (int i = 0; i < 4; i++)
#pragma unroll
                        for (int j = 0; j < 4; j++)
                            acc[ic][jc][i][j] += a[ic][i] * b[jc][j];
        }
        __syncthreads();
    }
#pragma unroll
    for (int ic = 0; ic < 2; ic++)
#pragma unroll
        for (int i = 0; i < 4; i++) {
            int m = m0 + ic * 64 + ty * 4 + i;
#pragma unroll
            for (int jc = 0; jc < 2; jc++) {
                int n = n0 + jc * 64 + tx * 4;
                float4 o;
                o.x = acc[ic][jc][i][0] + bias[n + 0];
                o.y = acc[ic][jc][i][1] + bias[n + 1];
                o.z = acc[ic][jc][i][2] + bias[n + 2];
                o.w = acc[ic][jc][i][3] + bias[n + 3];
                if (TANH) { o.x = tanhf(o.x); o.y = tanhf(o.y); o.z = tanhf(o.z); o.w = tanhf(o.w); }
                *(float4*)&C[(size_t)m * N + n] = o;
            }
        }
}

// ---------------- fused per-step kernel ----------------
// blocks [0,128):     GRU  gh = h_s @ W_hh^T (3 gates), epilogue -> h_{s+1}, outputs[s]
// blocks [128,160):   AUX  PV_s = tanh(h_s @ W_stk^T + b_stk)
// blocks [160,192):   ACT  P_s = softmax(h_s @ W_act^T + b_act)
// blocks [192,1216):  STACK update for step s-1 (uses P_{s-1}, PV_{s-1})
#define GRU_BLOCKS 128
#define AUX_BLOCKS 32
#define ACT_BLOCKS 32
#define STACK_BASE (GRU_BLOCKS + AUX_BLOCKS + ACT_BLOCKS)
#define STEP_BLOCKS (STACK_BASE + B_ * NSTACK)

__global__ void __launch_bounds__(256) step_kernel(
    int s,
    const int* __restrict__ tokens,
    const float* __restrict__ b_ih,
    const float* __restrict__ b_hh,
    const float* __restrict__ W_act,
    const float* __restrict__ b_act,
    const float* __restrict__ b_stk,
    const float* __restrict__ empty_elem,
    float* __restrict__ outputs,
    float* __restrict__ stacks)
{
    __shared__ float sm[4224];
    int tid = threadIdx.x;
    int blk = blockIdx.x;

    if (blk < GRU_BLOCKS) {
        if (s >= S_) return;
        const float* hin = g_h[s & 3];
        float* hout = g_h[(s + 1) & 3];
        float* As = sm;            // [32][33]
        float* Bs = sm + 1056;     // [3][32][32]
        int b0 = (blk >> 3) * 32;
        int j0 = (blk & 7) * 32;
        int tx = tid & 15, ty = tid >> 4;
        float acc[3][2][2] = {};
        for (int k0 = 0; k0 < H_; k0 += 32) {
            {   // A: coalesced float4, store transposed-access layout [m][k] pad 33
                int m = tid >> 3, q = (tid & 7) * 4;
                float4 v = *(const float4*)&hin[(b0 + m) * H_ + k0 + q];
                As[m * 33 + q + 0] = v.x; As[m * 33 + q + 1] = v.y;
                As[m * 33 + q + 2] = v.z; As[m * 33 + q + 3] = v.w;
            }
            {
                int kk = tid >> 3, jq = (tid & 7) * 4;
#pragma unroll
                for (int g = 0; g < 3; g++)
                    *(float4*)&Bs[(g * 32 + kk) * 32 + jq] =
                        *(const float4*)&g_WhhT[(k0 + kk) * H3 + g * H_ + j0 + jq];
            }
            __syncthreads();
#pragma unroll
            for (int kk = 0; kk < 32; kk++) {
                float a0 = As[(ty * 2) * 33 + kk];
                float a1 = As[(ty * 2 + 1) * 33 + kk];
#pragma unroll
                for (int g = 0; g < 3; g++) {
                    float2 bb = *(float2*)&Bs[(g * 32 + kk) * 32 + tx * 2];
                    acc[g][0][0] += a0 * bb.x; acc[g][0][1] += a0 * bb.y;
                    acc[g][1][0] += a1 * bb.x; acc[g][1][1] += a1 * bb.y;
                }
            }
            __syncthreads();
        }
#pragma unroll
        for (int i = 0; i < 2; i++) {
            int b = b0 + ty * 2 + i;
            int tok = tokens[s * B_ + b];
            const float* gi = (tok == 0) ? b_ih : (g_EMB_GI + (size_t)tok * H3);
#pragma unroll
            for (int j2 = 0; j2 < 2; j2++) {
                int j = j0 + tx * 2 + j2;
                float ghr = acc[0][i][j2] + b_hh[j];
                float ghz = acc[1][i][j2] + b_hh[H_ + j];
                float ghn = acc[2][i][j2] + b_hh[2 * H_ + j];
                float r = sigmoidf_(gi[j] + ghr);
                float z = sigmoidf_(gi[H_ + j] + ghz);
                float n = tanhf(gi[2 * H_ + j] + r * ghn);
                float hp = hin[b * H_ + j];
                float hn = (1.f - z) * n + z * hp;
                hout[b * H_ + j] = hn;
                outputs[((size_t)s * B_ + b) * H_ + j] = hn;
            }
        }
        return;
    }

    if (blk < GRU_BLOCKS + AUX_BLOCKS) {
        if (s >= S_) return;
        int ab = blk - GRU_BLOCKS;
        const float* hin = g_h[s & 3];
        float* pvout = g_PV[s & 1];
        int b0 = (ab >> 1) * 32;
        int c0 = (ab & 1) * 64;
        float* As = sm;          // [32][17]
        float* Bs = sm + 544;    // [16][64]
        int tx = tid & 15, ty = tid >> 4;
        float acc[2][4] = {};
        for (int k0 = 0; k0 < H_; k0 += 16) {
            {   // A coalesced float2, layout [m][k] pad 17
                int m = tid >> 3, q = (tid & 7) * 2;
                float2 v = *(const float2*)&hin[(b0 + m) * H_ + k0 + q];
                As[m * 17 + q] = v.x; As[m * 17 + q + 1] = v.y;
            }
            {
                int k = tid >> 4, nq = (tid & 15) * 4;
                *(float4*)&Bs[k * 64 + nq] =
                    *(const float4*)&g_WstkT[(k0 + k) * (NSTACK * ELEM) + c0 + nq];
            }
            __syncthreads();
#pragma unroll
            for (int kk = 0; kk < 16; kk++) {
                float a0 = As[(ty * 2) * 17 + kk];
                float a1 = As[(ty * 2 + 1) * 17 + kk];
                float4 bv = *(float4*)&Bs[kk * 64 + tx * 4];
                acc[0][0] += a0 * bv.x; acc[0][1] += a0 * bv.y;
                acc[0][2] += a0 * bv.z; acc[0][3] += a0 * bv.w;
                acc[1][0] += a1 * bv.x; acc[1][1] += a1 * bv.y;
                acc[1][2] += a1 * bv.z; acc[1][3] += a1 * bv.w;
            }
            __syncthreads();
        }
#pragma unroll
        for (int i = 0; i < 2; i++) {
            int b = b0 + ty * 2 + i;
#pragma unroll
            for (int j = 0; j < 4; j++) {
                int c = c0 + tx * 4 + j;
                pvout[b * (NSTACK * ELEM) + c] = tanhf(acc[i][j] + b_stk[c]);
            }
        }
        return;
    }

    if (blk < STACK_BASE) {
        // ---- ACT: act probs for step s ----
        if (s >= S_) return;
        int ab = blk - GRU_BLOCKS - AUX_BLOCKS;   // 0..31
        int b0 = ab * 16;
        const float* hin = g_h[s & 3];
        float* hsm = sm;                 // [16][257]
        float* logit = sm + 16 * 257;    // 96
        {
            int r = tid >> 4, c0 = (tid & 15) * 16;
#pragma unroll
            for (int q = 0; q < 4; q++) {
                float4 v = *(const float4*)&hin[(b0 + r) * H_ + c0 + q * 4];
                hsm[r * 257 + c0 + q * 4 + 0] = v.x;
                hsm[r * 257 + c0 + q * 4 + 1] = v.y;
                hsm[r * 257 + c0 + q * 4 + 2] = v.z;
                hsm[r * 257 + c0 + q * 4 + 3] = v.w;
            }
        }
        __syncthreads();
        if (tid < 96) {
            int bl = tid / 6, o = tid % 6;
            const float* wr = W_act + o * H_;
            float sum = b_act[o];
#pragma unroll 4
            for (int k = 0; k < H_; k++) sum += hsm[bl * 257 + k] * wr[k];
            logit[tid] = sum;
        }
        __syncthreads();
        if (tid < 32) {
            int bl = tid >> 1, n = tid & 1;
            float l0 = logit[bl * 6 + n * 3 + 0];
            float l1 = logit[bl * 6 + n * 3 + 1];
            float l2 = logit[bl * 6 + n * 3 + 2];
            float mx = fmaxf(l0, fmaxf(l1, l2));
            float e0 = expf(l0 - mx), e1 = expf(l1 - mx), e2 = expf(l2 - mx);
            float inv = 1.f / (e0 + e1 + e2);
            float* P = g_P[s & 1] + ((b0 + bl) * 2 + n) * 3;
            P[0] = e0 * inv; P[1] = e1 * inv; P[2] = e2 * inv;
        }
        return;
    }

    // ---- STACK update for step s-1 (register-resident) ----
    {
        if (s == 0) return;
        int sb = blk - STACK_BASE;
        int b = sb >> 1, n = sb & 1;
        const float* P = g_P[(s - 1) & 1] + (b * 2 + n) * 3;
        const float* pv = g_PV[(s - 1) & 1] + b * (NSTACK * ELEM) + n * ELEM;
        float* gst = stacks + ((size_t)(b * NSTACK + n) << 12);  // 64*64

        int e = tid & 63;
        int rb = (tid >> 6) * 16;
        float r[18];   // rows rb-1 .. rb+16
#pragma unroll
        for (int i = 0; i < 18; i++) {
            int row = rb - 1 + i;
            r[i] = (row >= 0 && row < SSIZE) ? gst[row * ELEM + e] : 0.f;
        }
        float ppush = P[0], ppop = P[1], pnoop = P[2];
        float pve = ppush * pv[e];
        float emp = empty_elem[e];
        __syncthreads();   // all reads done before any writes
#pragma unroll
        for (int i = 0; i < 16; i++) {
            int row = rb + i;
            float v;
            if (row == 0)            v = pve;
            else if (row == SSIZE-1) v = emp;
            else v = ppush * r[i] + ppop * r[i + 2] + pnoop * r[i + 1];
            gst[row * ELEM + e] = v;
        }
    }
}

// ---------------- attention scores ----------------
__global__ void score_k(const float* __restrict__ Wa2, const float* __restrict__ ba2,
                        const int* __restrict__ tokens) {
    int row = blockIdx.x * 8 + (threadIdx.x >> 5);
    int lane = threadIdx.x & 31;
    const float* t = g_T + (size_t)row * H_;
    float sum = 0.f;
#pragma unroll
    for (int k = lane; k < H_; k += 32) sum += t[k] * Wa2[k];
#pragma unroll
    for (int off = 16; off > 0; off >>= 1) sum += __shfl_xor_sync(0xffffffffu, sum, off);
    if (lane == 0) {
        float v = sum + ba2[0];
        if (tokens[row] == 0) v = -1e30f;
        g_scores[row] = v;
    }
}

// ---------------- softmax over S + weighted sum -> final_hidden ----------------
__global__ void __launch_bounds__(256) attn_final_k(const float* __restrict__ outputs,
                                                    float* __restrict__ fh) {
    int b = blockIdx.x;
    int tid = threadIdx.x;           // = s index / h index
    int lane = tid & 31, wid = tid >> 5;
    __shared__ float a_sm[S_];
    __shared__ float rmax[8];
    __shared__ float rsum[8];

    float v = g_scores[tid * B_ + b];
    float m = v;
#pragma unroll
    for (int off = 16; off > 0; off >>= 1) m = fmaxf(m, __shfl_xor_sync(0xffffffffu, m, off));
    if (lane == 0) rmax[wid] = m;
    __syncthreads();
    float mx = rmax[0];
#pragma unroll
    for (int i = 1; i < 8; i++) mx = fmaxf(mx, rmax[i]);
    float e = expf(v - mx);
    float sum = e;
#pragma unroll
    for (int off = 16; off > 0; off >>= 1) sum += __shfl_xor_sync(0xffffffffu, sum, off);
    if (lane == 0) rsum[wid] = sum;
    __syncthreads();
    float tot = rsum[0];
#pragma unroll
    for (int i = 1; i < 8; i++) tot += rsum[i];
    a_sm[tid] = e / tot;
    __syncthreads();

    float acc = 0.f;
    for (int s2 = 0; s2 < S_; s2++)
        acc += a_sm[s2] * outputs[((size_t)s2 * B_ + b) * H_ + tid];
    fh[b * H_ + tid] = acc;
}

// ---------------- launch ----------------
extern "C" void kernel_launch(void* const* d_in, const int* in_sizes, int n_in,
                              void* d_out, int out_size) {
    const int*   tokens     = (const int*)d_in[0];
    const float* emb        = (const float*)d_in[1];
    const float* W_ih       = (const float*)d_in[2];
    const float* W_hh       = (const float*)d_in[3];
    const float* b_ih       = (const float*)d_in[4];
    const float* b_hh       = (const float*)d_in[5];
    const float* W_act      = (const float*)d_in[6];
    const float* b_act      = (const float*)d_in[7];
    const float* W_stk      = (const float*)d_in[8];
    const float* b_stk      = (const float*)d_in[9];
    const float* empty_elem = (const float*)d_in[10];
    // d_in[11] = W_up, d_in[12] = W_down : shift matrices, hardcoded
    const float* Wa1        = (const float*)d_in[13];
    const float* ba1        = (const float*)d_in[14];
    const float* Wa2        = (const float*)d_in[15];
    const float* ba2        = (const float*)d_in[16];

    float* out     = (float*)d_out;
    float* outputs = out;
    float* fh      = out + (size_t)S_ * B_ * H_;
    float* stacks  = fh + (size_t)B_ * H_;

    float *pWihT, *pWa1T, *pEMB, *pT;
    cudaGetSymbolAddress((void**)&pWihT, g_WihT);
    cudaGetSymbolAddress((void**)&pWa1T, g_Wa1T);
    cudaGetSymbolAddress((void**)&pEMB,  g_EMB_GI);
    cudaGetSymbolAddress((void**)&pT,    g_T);

    // weight transposes
    transpose_k<<<(H3 * H_ + 255) / 256, 256>>>(W_ih, 0, H3, H_);
    transpose_k<<<(H3 * H_ + 255) / 256, 256>>>(W_hh, 1, H3, H_);
    transpose_k<<<(NSTACK * ELEM * H_ + 255) / 256, 256>>>(W_stk, 2, NSTACK * ELEM, H_);
    transpose_k<<<(H_ * H_ + 255) / 256, 256>>>(Wa1, 3, H_, H_);

    // init h0 and stacks
    init_k<<<(B_ * NSTACK * SSIZE * ELEM + 255) / 256, 256>>>(stacks, empty_elem);

    // EMB_GI = emb @ W_ih^T + b_ih  (32000 x 768)
    {
        dim3 grid(H3 / 128, VOCAB_ / 128);
        sgemm128_k<false><<<grid, 256>>>(emb, pWihT, b_ih, pEMB, VOCAB_, H3, H_);
    }

    // recurrence: 256 steps + 1 tail launch for the final stack update
    for (int s = 0; s <= S_; s++) {
        step_kernel<<<STEP_BLOCKS, 256>>>(s, tokens, b_ih, b_hh, W_act, b_act,
                                          b_stk, empty_elem, outputs, stacks);
    }

    // attention
    {
        dim3 grid(H_ / 128, (S_ * B_) / 128);
        sgemm128_k<true><<<grid, 256>>>(outputs, pWa1T, ba1, pT, S_ * B_, H_, H_);
    }
    score_k<<<(S_ * B_) / 8, 256>>>(Wa2, ba2, tokens);
    attn_final_k<<<B_, 256>>>(outputs, fh);
}